// round 1
// baseline (speedup 1.0000x reference)
#include <cuda_runtime.h>
#include <math.h>

#define BATCH 4
#define SEQ 4096
#define EMBED 1024
#define PROJ 128
#define MTOT (BATCH*SEQ)   // 16384

// Scratch (device globals: allocation-free per harness rules)
__device__ float g_Q[(size_t)MTOT*PROJ];                // 8 MB
__device__ float g_K[(size_t)MTOT*PROJ];                // 8 MB
__device__ float g_OV[(size_t)MTOT*EMBED];              // 64 MB
__device__ float g_S[(size_t)BATCH*SEQ*SEQ];            // 256 MB

// Generic tiled SGEMM: C = alpha * A @ op(B) + bias
//   A: [M,K] row-major, B: [K,N] (transB=0) or [N,K] (transB=1), C: [M,N]
//   All of M,N multiples of 128; K multiple of 16 (true for every call here).
//   Batched via blockIdx.z with element strides sA/sB/sC.
__global__ __launch_bounds__(256)
void sgemm128(const float* __restrict__ A, const float* __restrict__ B,
              const float* __restrict__ bias, float* __restrict__ C,
              int M, int N, int K, float alpha, int transB,
              long sA, long sB, long sC)
{
    A += (long)blockIdx.z * sA;
    B += (long)blockIdx.z * sB;
    C += (long)blockIdx.z * sC;

    __shared__ float As[16][128];
    __shared__ float Bs[16][128];

    const int tid = threadIdx.x;
    const int m0 = blockIdx.y * 128;
    const int n0 = blockIdx.x * 128;

    // Warp layout: 8 warps as 4 (rows) x 2 (cols); lanes as 4 (rows) x 8 (cols).
    // Each thread owns rows {trow..trow+3, trow+16..trow+19}
    //            and cols {tcol..tcol+3, tcol+32..tcol+35}.
    const int warp = tid >> 5, lane = tid & 31;
    const int wm = warp >> 1, wn = warp & 1;
    const int by = lane >> 3, bx = lane & 7;
    const int trow = wm * 32 + by * 4;
    const int tcol = wn * 64 + bx * 4;

    float acc[2][2][4][4];
    #pragma unroll
    for (int i = 0; i < 2; i++)
        #pragma unroll
        for (int j = 0; j < 2; j++)
            #pragma unroll
            for (int r = 0; r < 4; r++)
                #pragma unroll
                for (int c = 0; c < 4; c++)
                    acc[i][j][r][c] = 0.f;

    for (int k0 = 0; k0 < K; k0 += 16) {
        // --- load A tile (128 x 16), stored transposed As[k][m] ---
        #pragma unroll
        for (int j = 0; j < 2; j++) {
            int idx = tid + j * 256;            // 512 float4s
            int ar = idx >> 2;                  // 0..127
            int ac = (idx & 3) * 4;             // 0,4,8,12
            float4 v = *(const float4*)&A[(long)(m0 + ar) * K + k0 + ac];
            As[ac + 0][ar] = v.x; As[ac + 1][ar] = v.y;
            As[ac + 2][ar] = v.z; As[ac + 3][ar] = v.w;
        }
        // --- load B tile -> Bs[k][n] ---
        if (!transB) {
            #pragma unroll
            for (int j = 0; j < 2; j++) {
                int idx = tid + j * 256;
                int br = idx >> 5;              // 0..15  (k)
                int bc = (idx & 31) * 4;        // 0..124 (n)
                float4 v = *(const float4*)&B[(long)(k0 + br) * N + n0 + bc];
                *(float4*)&Bs[br][bc] = v;
            }
        } else {
            #pragma unroll
            for (int j = 0; j < 2; j++) {
                int idx = tid + j * 256;
                int br = idx >> 2;              // 0..127 (n)
                int bc = (idx & 3) * 4;         // 0..12  (k)
                float4 v = *(const float4*)&B[(long)(n0 + br) * K + k0 + bc];
                Bs[bc + 0][br] = v.x; Bs[bc + 1][br] = v.y;
                Bs[bc + 2][br] = v.z; Bs[bc + 3][br] = v.w;
            }
        }
        __syncthreads();

        #pragma unroll
        for (int k = 0; k < 16; k++) {
            float4 a0 = *(const float4*)&As[k][trow];
            float4 a1 = *(const float4*)&As[k][trow + 16];
            float4 b0 = *(const float4*)&Bs[k][tcol];
            float4 b1 = *(const float4*)&Bs[k][tcol + 32];
            float a[2][4] = {{a0.x, a0.y, a0.z, a0.w}, {a1.x, a1.y, a1.z, a1.w}};
            float b[2][4] = {{b0.x, b0.y, b0.z, b0.w}, {b1.x, b1.y, b1.z, b1.w}};
            #pragma unroll
            for (int i = 0; i < 2; i++)
                #pragma unroll
                for (int r = 0; r < 4; r++)
                    #pragma unroll
                    for (int j = 0; j < 2; j++)
                        #pragma unroll
                        for (int c = 0; c < 4; c++)
                            acc[i][j][r][c] += a[i][r] * b[j][c];
        }
        __syncthreads();
    }

    // --- epilogue: alpha + bias, float4 stores (coalesced per lane phase) ---
    #pragma unroll
    for (int j = 0; j < 2; j++) {
        int col = n0 + tcol + j * 32;
        float4 bv = make_float4(0.f, 0.f, 0.f, 0.f);
        if (bias) bv = *(const float4*)&bias[col];
        #pragma unroll
        for (int i = 0; i < 2; i++) {
            #pragma unroll
            for (int r = 0; r < 4; r++) {
                int row = m0 + trow + i * 16 + r;
                float4 o;
                o.x = alpha * acc[i][j][r][0] + bv.x;
                o.y = alpha * acc[i][j][r][1] + bv.y;
                o.z = alpha * acc[i][j][r][2] + bv.z;
                o.w = alpha * acc[i][j][r][3] + bv.w;
                *(float4*)&C[(long)row * N + col] = o;
            }
        }
    }
}

// Row softmax over 4096-wide rows; one CTA (256 threads) per row, data held in
// registers across the max / exp-sum / normalize phases.
__global__ __launch_bounds__(256)
void softmax4096(float* __restrict__ S)
{
    float* row = S + (size_t)blockIdx.x * 4096;
    const int tid = threadIdx.x;

    float4 v[4];
    float m = -1e30f;
    #pragma unroll
    for (int i = 0; i < 4; i++) {
        v[i] = ((const float4*)row)[tid + i * 256];
        m = fmaxf(m, fmaxf(fmaxf(v[i].x, v[i].y), fmaxf(v[i].z, v[i].w)));
    }

    __shared__ float red[8];
    #pragma unroll
    for (int o = 16; o > 0; o >>= 1)
        m = fmaxf(m, __shfl_xor_sync(0xffffffffu, m, o));
    if ((tid & 31) == 0) red[tid >> 5] = m;
    __syncthreads();
    m = red[0];
    #pragma unroll
    for (int w = 1; w < 8; w++) m = fmaxf(m, red[w]);

    float s = 0.f;
    #pragma unroll
    for (int i = 0; i < 4; i++) {
        v[i].x = expf(v[i].x - m); v[i].y = expf(v[i].y - m);
        v[i].z = expf(v[i].z - m); v[i].w = expf(v[i].w - m);
        s += v[i].x + v[i].y + v[i].z + v[i].w;
    }
    #pragma unroll
    for (int o = 16; o > 0; o >>= 1)
        s += __shfl_xor_sync(0xffffffffu, s, o);
    __syncthreads();            // red reuse
    if ((tid & 31) == 0) red[tid >> 5] = s;
    __syncthreads();
    s = 0.f;
    #pragma unroll
    for (int w = 0; w < 8; w++) s += red[w];

    float inv = 1.f / s;
    #pragma unroll
    for (int i = 0; i < 4; i++) {
        v[i].x *= inv; v[i].y *= inv; v[i].z *= inv; v[i].w *= inv;
        ((float4*)row)[tid + i * 256] = v[i];
    }
}

extern "C" void kernel_launch(void* const* d_in, const int* in_sizes, int n_in,
                              void* d_out, int out_size)
{
    const float* x   = (const float*)d_in[0];
    const float* Wq  = (const float*)d_in[1];
    const float* bq  = (const float*)d_in[2];
    const float* Wk  = (const float*)d_in[3];
    const float* bk  = (const float*)d_in[4];
    const float* Wov = (const float*)d_in[5];
    const float* bov = (const float*)d_in[6];
    float* out = (float*)d_out;

    float *Q, *Kp, *OV, *S;
    cudaGetSymbolAddress((void**)&Q,  g_Q);
    cudaGetSymbolAddress((void**)&Kp, g_K);
    cudaGetSymbolAddress((void**)&OV, g_OV);
    cudaGetSymbolAddress((void**)&S,  g_S);

    dim3 blk(256);
    const float scale = 0.08838834764831845f;   // 1/sqrt(128)

    // Projections: Q, K (N=128), OV (N=1024)
    sgemm128<<<dim3(PROJ / 128, MTOT / 128, 1), blk>>>(
        x, Wq, bq, Q, MTOT, PROJ, EMBED, 1.f, 0, 0, 0, 0);
    sgemm128<<<dim3(PROJ / 128, MTOT / 128, 1), blk>>>(
        x, Wk, bk, Kp, MTOT, PROJ, EMBED, 1.f, 0, 0, 0, 0);
    sgemm128<<<dim3(EMBED / 128, MTOT / 128, 1), blk>>>(
        x, Wov, bov, OV, MTOT, EMBED, EMBED, 1.f, 0, 0, 0, 0);

    // Scores: S[b] = (Q[b] @ K[b]^T) / sqrt(128)
    sgemm128<<<dim3(SEQ / 128, SEQ / 128, BATCH), blk>>>(
        Q, Kp, nullptr, S, SEQ, SEQ, PROJ, scale, 1,
        (long)SEQ * PROJ, (long)SEQ * PROJ, (long)SEQ * SEQ);

    // Softmax over last dim
    softmax4096<<<BATCH * SEQ, 256>>>(S);

    // Output: out[b] = P[b] @ OV[b]
    sgemm128<<<dim3(EMBED / 128, SEQ / 128, BATCH), blk>>>(
        S, OV, nullptr, out, SEQ, EMBED, SEQ, 1.f, 0,
        (long)SEQ * SEQ, (long)SEQ * EMBED, (long)SEQ * EMBED);
}

// round 2
// speedup vs baseline: 1.5773x; 1.5773x over previous
#include <cuda_runtime.h>
#include <math.h>

#define BATCH 4
#define SEQ 4096
#define EMBED 1024
#define PROJ 128
#define MTOT (BATCH*SEQ)   // 16384

// Scratch (device globals: allocation-free per harness rules)
__device__ float g_Q[(size_t)MTOT*PROJ];                // 8 MB
__device__ float g_K[(size_t)MTOT*PROJ];                // 8 MB
__device__ float g_OV[(size_t)MTOT*EMBED];              // 64 MB
__device__ float g_S[(size_t)BATCH*SEQ*SEQ];            // 256 MB

// Generic tiled SGEMM: C = alpha * A @ op(B) + bias
//   A: [M,K] row-major, B: [K,N] (transB=0) or [N,K] (transB=1), C: [M,N]
//   All of M,N multiples of 128; K multiple of 16 (true for every call here).
//   Batched via blockIdx.z with element strides sA/sB/sC.
__global__ __launch_bounds__(256)
void sgemm128(const float* __restrict__ A, const float* __restrict__ B,
              const float* __restrict__ bias, float* __restrict__ C,
              int M, int N, int K, float alpha, int transB,
              long sA, long sB, long sC)
{
    A += (long)blockIdx.z * sA;
    B += (long)blockIdx.z * sB;
    C += (long)blockIdx.z * sC;

    __shared__ float As[16][128];
    __shared__ float Bs[16][128];

    const int tid = threadIdx.x;
    const int m0 = blockIdx.y * 128;
    const int n0 = blockIdx.x * 128;

    // Warp layout: 8 warps as 4 (rows) x 2 (cols); lanes as 4 (rows) x 8 (cols).
    // Each thread owns rows {trow..trow+3, trow+16..trow+19}
    //            and cols {tcol..tcol+3, tcol+32..tcol+35}.
    const int warp = tid >> 5, lane = tid & 31;
    const int wm = warp >> 1, wn = warp & 1;
    const int by = lane >> 3, bx = lane & 7;
    const int trow = wm * 32 + by * 4;
    const int tcol = wn * 64 + bx * 4;

    float acc[2][2][4][4];
    #pragma unroll
    for (int i = 0; i < 2; i++)
        #pragma unroll
        for (int j = 0; j < 2; j++)
            #pragma unroll
            for (int r = 0; r < 4; r++)
                #pragma unroll
                for (int c = 0; c < 4; c++)
                    acc[i][j][r][c] = 0.f;

    for (int k0 = 0; k0 < K; k0 += 16) {
        // --- load A tile (128 x 16), stored transposed As[k][m] ---
        #pragma unroll
        for (int j = 0; j < 2; j++) {
            int idx = tid + j * 256;            // 512 float4s
            int ar = idx >> 2;                  // 0..127
            int ac = (idx & 3) * 4;             // 0,4,8,12
            float4 v = *(const float4*)&A[(long)(m0 + ar) * K + k0 + ac];
            As[ac + 0][ar] = v.x; As[ac + 1][ar] = v.y;
            As[ac + 2][ar] = v.z; As[ac + 3][ar] = v.w;
        }
        // --- load B tile -> Bs[k][n] ---
        if (!transB) {
            #pragma unroll
            for (int j = 0; j < 2; j++) {
                int idx = tid + j * 256;
                int br = idx >> 5;              // 0..15  (k)
                int bc = (idx & 31) * 4;        // 0..124 (n)
                float4 v = *(const float4*)&B[(long)(k0 + br) * N + n0 + bc];
                *(float4*)&Bs[br][bc] = v;
            }
        } else {
            #pragma unroll
            for (int j = 0; j < 2; j++) {
                int idx = tid + j * 256;
                int br = idx >> 2;              // 0..127 (n)
                int bc = (idx & 3) * 4;         // 0..12  (k)
                float4 v = *(const float4*)&B[(long)(n0 + br) * K + k0 + bc];
                Bs[bc + 0][br] = v.x; Bs[bc + 1][br] = v.y;
                Bs[bc + 2][br] = v.z; Bs[bc + 3][br] = v.w;
            }
        }
        __syncthreads();

        #pragma unroll
        for (int k = 0; k < 16; k++) {
            float4 a0 = *(const float4*)&As[k][trow];
            float4 a1 = *(const float4*)&As[k][trow + 16];
            float4 b0 = *(const float4*)&Bs[k][tcol];
            float4 b1 = *(const float4*)&Bs[k][tcol + 32];
            float a[2][4] = {{a0.x, a0.y, a0.z, a0.w}, {a1.x, a1.y, a1.z, a1.w}};
            float b[2][4] = {{b0.x, b0.y, b0.z, b0.w}, {b1.x, b1.y, b1.z, b1.w}};
            #pragma unroll
            for (int i = 0; i < 2; i++)
                #pragma unroll
                for (int r = 0; r < 4; r++)
                    #pragma unroll
                    for (int j = 0; j < 2; j++)
                        #pragma unroll
                        for (int c = 0; c < 4; c++)
                            acc[i][j][r][c] += a[i][r] * b[j][c];
        }
        __syncthreads();
    }

    // --- epilogue: alpha + bias, float4 stores (coalesced per lane phase) ---
    #pragma unroll
    for (int j = 0; j < 2; j++) {
        int col = n0 + tcol + j * 32;
        float4 bv = make_float4(0.f, 0.f, 0.f, 0.f);
        if (bias) bv = *(const float4*)&bias[col];
        #pragma unroll
        for (int i = 0; i < 2; i++) {
            #pragma unroll
            for (int r = 0; r < 4; r++) {
                int row = m0 + trow + i * 16 + r;
                float4 o;
                o.x = alpha * acc[i][j][r][0] + bv.x;
                o.y = alpha * acc[i][j][r][1] + bv.y;
                o.z = alpha * acc[i][j][r][2] + bv.z;
                o.w = alpha * acc[i][j][r][3] + bv.w;
                *(float4*)&C[(long)row * N + col] = o;
            }
        }
    }
}

// Row softmax over 4096-wide rows; one CTA (256 threads) per row, data held in
// registers across the max / exp-sum / normalize phases.
__global__ __launch_bounds__(256)
void softmax4096(float* __restrict__ S)
{
    float* row = S + (size_t)blockIdx.x * 4096;
    const int tid = threadIdx.x;

    float4 v[4];
    float m = -1e30f;
    #pragma unroll
    for (int i = 0; i < 4; i++) {
        v[i] = ((const float4*)row)[tid + i * 256];
        m = fmaxf(m, fmaxf(fmaxf(v[i].x, v[i].y), fmaxf(v[i].z, v[i].w)));
    }

    __shared__ float red[8];
    #pragma unroll
    for (int o = 16; o > 0; o >>= 1)
        m = fmaxf(m, __shfl_xor_sync(0xffffffffu, m, o));
    if ((tid & 31) == 0) red[tid >> 5] = m;
    __syncthreads();
    m = red[0];
    #pragma unroll
    for (int w = 1; w < 8; w++) m = fmaxf(m, red[w]);

    float s = 0.f;
    #pragma unroll
    for (int i = 0; i < 4; i++) {
        v[i].x = expf(v[i].x - m); v[i].y = expf(v[i].y - m);
        v[i].z = expf(v[i].z - m); v[i].w = expf(v[i].w - m);
        s += v[i].x + v[i].y + v[i].z + v[i].w;
    }
    #pragma unroll
    for (int o = 16; o > 0; o >>= 1)
        s += __shfl_xor_sync(0xffffffffu, s, o);
    __syncthreads();            // red reuse
    if ((tid & 31) == 0) red[tid >> 5] = s;
    __syncthreads();
    s = 0.f;
    #pragma unroll
    for (int w = 0; w < 8; w++) s += red[w];

    float inv = 1.f / s;
    #pragma unroll
    for (int i = 0; i < 4; i++) {
        v[i].x *= inv; v[i].y *= inv; v[i].z *= inv; v[i].w *= inv;
        ((float4*)row)[tid + i * 256] = v[i];
    }
}

extern "C" void kernel_launch(void* const* d_in, const int* in_sizes, int n_in,
                              void* d_out, int out_size)
{
    const float* x   = (const float*)d_in[0];
    const float* Wq  = (const float*)d_in[1];
    const float* bq  = (const float*)d_in[2];
    const float* Wk  = (const float*)d_in[3];
    const float* bk  = (const float*)d_in[4];
    const float* Wov = (const float*)d_in[5];
    const float* bov = (const float*)d_in[6];
    float* out = (float*)d_out;

    float *Q, *Kp, *OV, *S;
    cudaGetSymbolAddress((void**)&Q,  g_Q);
    cudaGetSymbolAddress((void**)&Kp, g_K);
    cudaGetSymbolAddress((void**)&OV, g_OV);
    cudaGetSymbolAddress((void**)&S,  g_S);

    dim3 blk(256);
    const float scale = 0.08838834764831845f;   // 1/sqrt(128)

    // Projections: Q, K (N=128), OV (N=1024)
    sgemm128<<<dim3(PROJ / 128, MTOT / 128, 1), blk>>>(
        x, Wq, bq, Q, MTOT, PROJ, EMBED, 1.f, 0, 0, 0, 0);
    sgemm128<<<dim3(PROJ / 128, MTOT / 128, 1), blk>>>(
        x, Wk, bk, Kp, MTOT, PROJ, EMBED, 1.f, 0, 0, 0, 0);
    sgemm128<<<dim3(EMBED / 128, MTOT / 128, 1), blk>>>(
        x, Wov, bov, OV, MTOT, EMBED, EMBED, 1.f, 0, 0, 0, 0);

    // Scores: S[b] = (Q[b] @ K[b]^T) / sqrt(128)
    sgemm128<<<dim3(SEQ / 128, SEQ / 128, BATCH), blk>>>(
        Q, Kp, nullptr, S, SEQ, SEQ, PROJ, scale, 1,
        (long)SEQ * PROJ, (long)SEQ * PROJ, (long)SEQ * SEQ);

    // Softmax over last dim
    softmax4096<<<BATCH * SEQ, 256>>>(S);

    // Output: out[b] = P[b] @ OV[b]
    sgemm128<<<dim3(EMBED / 128, SEQ / 128, BATCH), blk>>>(
        S, OV, nullptr, out, SEQ, EMBED, SEQ, 1.f, 0,
        (long)SEQ * SEQ, (long)SEQ * EMBED, (long)SEQ * EMBED);
}

// round 5
// speedup vs baseline: 12.9676x; 8.2213x over previous
#include <cuda_runtime.h>
#include <cuda.h>
#include <cstdint>
#include <math.h>

#define BATCH 4
#define SEQ 4096
#define EMBED 1024
#define PROJ 128
#define MTOT (BATCH*SEQ)   // 16384

// tcgen05 is an arch-SPECIFIC feature: only present when compiling for
// sm_103a / sm_100a. The harness also emits a plain compute_103 PTX pass,
// which must not see these instructions (kernel body compiles empty there;
// the runtime always selects the sm_103a SASS on-chip).
#if defined(__CUDA_ARCH__) && (defined(__CUDA_ARCH_FEAT_SM103_ALL) || defined(__CUDA_ARCH_FEAT_SM100_ALL))
#define TC_OK 1
#else
#define TC_OK 0
#endif

// ---------------- scratch (device globals; allocation-free) ----------------
__device__ float g_QK [(size_t)MTOT*256];          // 16 MB  (Q | K concat, tf32-RN)
__device__ float g_OVt[(size_t)EMBED*MTOT];        // 64 MB  (OV^T [embed][token], tf32-RN)
__device__ float g_S  [(size_t)BATCH*SEQ*SEQ];     // 256 MB (scores / pattern)
__device__ float g_Wqk[256*EMBED];                 // Wq^T ; Wk^T stacked (tf32-RN)
__device__ float g_bqk[256];
__device__ float g_Wovt[(size_t)EMBED*EMBED];      // Wov^T (tf32-RN)

// ---------------- tile config ----------------
#define MT 128
#define NT 256
#define KC 32
#define ST 4
#define STAGE_A_BYTES (MT*128)                 // 16384
#define STAGE_B_BYTES (NT*128)                 // 32768
#define STAGE_BYTES   (STAGE_A_BYTES + STAGE_B_BYTES)
#define CTRL_BYTES    1024
#define SMEM_TOTAL    (CTRL_BYTES + ST*STAGE_BYTES)

// idesc (kind::tf32): dtype=F32(1)<<4, atype=TF32(2)<<7, btype=TF32(2)<<10,
// N/8<<17, M/16<<24; K-major both sides.
#define TC_IDESC ((1u<<4) | (2u<<7) | (2u<<10) | ((NT/8u)<<17) | ((MT/16u)<<24))

__device__ __forceinline__ uint32_t smem_u32(const void* p) {
    uint32_t a;
    asm("{ .reg .u64 t; cvta.to.shared.u64 t, %1; cvt.u32.u64 %0, t; }" : "=r"(a) : "l"(p));
    return a;
}

__device__ __forceinline__ float rtf32(float x) {
#if TC_OK
    float y; asm("cvt.rn.tf32.f32 %0, %1;" : "=f"(y) : "f"(x)); return y;
#else
    // numerically-equivalent RN-to-tf32 emulation for the generic PTX pass
    unsigned u = __float_as_uint(x);
    unsigned r = (u + 0x1000u + ((u >> 13) & 1u)) & 0xFFFFE000u;
    return __uint_as_float(r);
#endif
}

#if TC_OK
// SW128 K-major smem descriptor: LBO=1, SBO=64, version=1, layout=2
__device__ __forceinline__ uint64_t make_desc(uint32_t addr) {
    const uint64_t base = (uint64_t(2) << 61) | (uint64_t(1) << 46)
                        | (uint64_t(64) << 32) | (uint64_t(1) << 16);
    return base | ((uint64_t)(addr >> 4) & 0x3FFF);
}

#define MBAR_INIT(a, c) \
    asm volatile("mbarrier.init.shared.b64 [%0], %1;" :: "r"(a), "r"(c) : "memory")
#define MBAR_EXPECT(a, b) \
    asm volatile("mbarrier.arrive.expect_tx.shared.b64 _, [%0], %1;" :: "r"(a), "r"(b) : "memory")
#define MBAR_WAIT(a, ph) do { \
    asm volatile("{\n\t.reg .pred P1;\n\t" \
        "WL_%=:\n\t" \
        "mbarrier.try_wait.parity.acquire.cta.shared::cta.b64 P1, [%0], %1, 0x989680;\n\t" \
        "@P1 bra WD_%=;\n\t" \
        "bra WL_%=;\n\t" \
        "WD_%=:\n\t}" \
        :: "r"(a), "r"(ph) : "memory"); \
} while (0)

__device__ __forceinline__ void tma2d(uint32_t dst, const CUtensorMap* m,
                                      int x, int y, uint32_t bar) {
    asm volatile(
        "cp.async.bulk.tensor.2d.shared::cta.global.tile.mbarrier::complete_tx::bytes "
        "[%0], [%1, {%2, %3}], [%4];"
        :: "r"(dst), "l"(m), "r"(x), "r"(y), "r"(bar) : "memory");
}

__device__ __forceinline__ void mma_tf32(uint32_t d, uint64_t ad, uint64_t bd,
                                         uint32_t idesc, uint32_t en) {
    asm volatile(
        "{\n\t.reg .pred p;\n\tsetp.ne.u32 p, %4, 0;\n\t"
        "tcgen05.mma.cta_group::1.kind::tf32 [%0], %1, %2, %3, {%5, %5, %5, %5}, p;\n\t}"
        :: "r"(d), "l"(ad), "l"(bd), "r"(idesc), "r"(en), "r"(0u) : "memory");
}

#define TC_COMMIT(bar) \
    asm volatile("tcgen05.commit.cta_group::1.mbarrier::arrive::one.shared::cluster.b64 [%0];" \
                 :: "r"(bar) : "memory")
#define TC_ALLOC(slot, n) \
    asm volatile("tcgen05.alloc.cta_group::1.sync.aligned.shared::cta.b32 [%0], %1;" \
                 :: "r"(slot), "r"(n) : "memory")
#define TC_DEALLOC(t, n) \
    asm volatile("tcgen05.dealloc.cta_group::1.sync.aligned.b32 %0, %1;" :: "r"(t), "r"(n))
#define TC_RELINQ() \
    asm volatile("tcgen05.relinquish_alloc_permit.cta_group::1.sync.aligned;")
#define TC_FENCE_AFTER()  asm volatile("tcgen05.fence::after_thread_sync;" ::: "memory")
#define TC_FENCE_BEFORE() asm volatile("tcgen05.fence::before_thread_sync;" ::: "memory")
#define TC_WAIT_LD()      asm volatile("tcgen05.wait::ld.sync.aligned;" ::: "memory")

#define TC_LD_X32(r, addr) \
    asm volatile( \
        "tcgen05.ld.sync.aligned.32x32b.x32.b32 " \
        "{%0, %1, %2, %3, %4, %5, %6, %7, " \
        " %8, %9, %10, %11, %12, %13, %14, %15, " \
        " %16, %17, %18, %19, %20, %21, %22, %23, " \
        " %24, %25, %26, %27, %28, %29, %30, %31}, [%32];" \
        : "=r"((r)[0]),  "=r"((r)[1]),  "=r"((r)[2]),  "=r"((r)[3]), \
          "=r"((r)[4]),  "=r"((r)[5]),  "=r"((r)[6]),  "=r"((r)[7]), \
          "=r"((r)[8]),  "=r"((r)[9]),  "=r"((r)[10]), "=r"((r)[11]), \
          "=r"((r)[12]), "=r"((r)[13]), "=r"((r)[14]), "=r"((r)[15]), \
          "=r"((r)[16]), "=r"((r)[17]), "=r"((r)[18]), "=r"((r)[19]), \
          "=r"((r)[20]), "=r"((r)[21]), "=r"((r)[22]), "=r"((r)[23]), \
          "=r"((r)[24]), "=r"((r)[25]), "=r"((r)[26]), "=r"((r)[27]), \
          "=r"((r)[28]), "=r"((r)[29]), "=r"((r)[30]), "=r"((r)[31]) \
        : "r"(addr))
#endif  // TC_OK

// ---------------------------------------------------------------------------
// tcgen05 tf32 GEMM:  C[128 x 256 tile] = alpha * A @ B^T (+bias)
// A via mapA (box 32x128), B via mapB (box 32x256); both K-major fp32 SW128.
// ---------------------------------------------------------------------------
__global__ void __launch_bounds__(256, 1) tc_gemm(
    const __grid_constant__ CUtensorMap mapA,
    const __grid_constant__ CUtensorMap mapB,
    const float* __restrict__ bias, float* __restrict__ C,
    int K, int xA0, int xB0, int szBx, int szAy, int szBy,
    int ldc, long szC, float alpha, int transStore, int roundOut)
{
#if TC_OK
    extern __shared__ __align__(1024) char smem[];
    const uint32_t sb = smem_u32(smem);
    const int tid = threadIdx.x, wid = tid >> 5;
    const int z = blockIdx.z;
    const int KT = K / KC;

    // ctrl: full[s]@s*16, empty[s]@s*16+8, done@64, tmem-slot@96
    if (tid == 0) {
        #pragma unroll
        for (int s = 0; s < ST; s++) {
            MBAR_INIT(sb + s*16,     1);   // full
            MBAR_INIT(sb + s*16 + 8, 1);   // empty
        }
        MBAR_INIT(sb + 64, 1);             // done
    }
    if (wid == 0) TC_ALLOC(sb + 96, 256);
    __syncthreads();
    uint32_t tmem;
    asm volatile("ld.shared.b32 %0, [%1];" : "=r"(tmem) : "r"(sb + 96));

    if (tid == 224) {
        // ---- producer: single thread, TMA feeds ring ----
        const int yA = blockIdx.y * MT + z * szAy;
        const int yB = blockIdx.x * NT + z * szBy;
        const int xB = xB0 + z * szBx;
        int s = 0, ph = 1;
        for (int kt = 0; kt < KT; kt++) {
            MBAR_WAIT(sb + s*16 + 8, ph);             // empty
            MBAR_EXPECT(sb + s*16, STAGE_BYTES);
            const uint32_t stg = sb + CTRL_BYTES + s * STAGE_BYTES;
            tma2d(stg,                 &mapA, xA0 + kt*KC, yA, sb + s*16);
            tma2d(stg + STAGE_A_BYTES, &mapB, xB  + kt*KC, yB, sb + s*16);
            if (++s == ST) { s = 0; ph ^= 1; }
        }
    } else if (tid == 192) {
        // ---- consumer: single thread issues MMAs ----
        uint64_t ad[ST], bd[ST];
        #pragma unroll
        for (int s = 0; s < ST; s++) {
            ad[s] = make_desc(sb + CTRL_BYTES + s * STAGE_BYTES);
            bd[s] = make_desc(sb + CTRL_BYTES + s * STAGE_BYTES + STAGE_A_BYTES);
        }
        int s = 0, ph = 0;
        for (int kt = 0; kt < KT; kt++) {
            MBAR_WAIT(sb + s*16, ph);                 // full
            #pragma unroll
            for (int j = 0; j < 4; j++)               // 4 x K=8 per 32-K stage
                mma_tf32(tmem, ad[s] + j*2, bd[s] + j*2, TC_IDESC,
                         (uint32_t)((kt | j) != 0));
            TC_COMMIT(sb + s*16 + 8);                 // -> empty[s]
            if (++s == ST) { s = 0; ph ^= 1; }
        }
        TC_COMMIT(sb + 64);                           // -> done
    }

    MBAR_WAIT(sb + 64, 0);
    TC_FENCE_AFTER();

    // ---- epilogue: warps 0-3 read TMEM; lane m = tid (0..127) ----
    if (wid < 4) {
        const int ml = tid;
        float* Cz = C + (long)z * szC;
        #pragma unroll
        for (int nc = 0; nc < NT/32; nc++) {
            uint32_t r[32];
            TC_LD_X32(r, tmem + nc*32);
            TC_WAIT_LD();
            const int nbase = blockIdx.x * NT + nc * 32;
            if (!transStore) {
                float4* dst = (float4*)(Cz + ((long)blockIdx.y*MT + ml) * ldc + nbase);
                #pragma unroll
                for (int j = 0; j < 8; j++) {
                    float4 bv = make_float4(0.f, 0.f, 0.f, 0.f);
                    if (bias) bv = *(const float4*)(bias + nbase + 4*j);
                    float4 o;
                    o.x = alpha * __uint_as_float(r[4*j+0]) + bv.x;
                    o.y = alpha * __uint_as_float(r[4*j+1]) + bv.y;
                    o.z = alpha * __uint_as_float(r[4*j+2]) + bv.z;
                    o.w = alpha * __uint_as_float(r[4*j+3]) + bv.w;
                    if (roundOut) { o.x=rtf32(o.x); o.y=rtf32(o.y); o.z=rtf32(o.z); o.w=rtf32(o.w); }
                    dst[j] = o;
                }
            } else {
                #pragma unroll
                for (int i = 0; i < 32; i++) {
                    const int n = nbase + i;
                    float v = alpha * __uint_as_float(r[i]) + (bias ? __ldg(bias + n) : 0.f);
                    if (roundOut) v = rtf32(v);
                    Cz[(long)n * ldc + blockIdx.y*MT + ml] = v;  // coalesced across lanes
                }
            }
        }
        TC_FENCE_BEFORE();
    }
    __syncthreads();
    if (wid == 0) { TC_RELINQ(); TC_DEALLOC(tmem, 256); }
#endif  // TC_OK
}

// ---------------- softmax over 4096-wide rows (tf32-RN output) -------------
__global__ void __launch_bounds__(256) softmax4096(float* __restrict__ S)
{
    float* row = S + (size_t)blockIdx.x * 4096;
    const int tid = threadIdx.x;

    float4 v[4];
    float m = -1e30f;
    #pragma unroll
    for (int i = 0; i < 4; i++) {
        v[i] = ((const float4*)row)[tid + i*256];
        m = fmaxf(m, fmaxf(fmaxf(v[i].x, v[i].y), fmaxf(v[i].z, v[i].w)));
    }
    __shared__ float red[8];
    #pragma unroll
    for (int o = 16; o > 0; o >>= 1) m = fmaxf(m, __shfl_xor_sync(~0u, m, o));
    if ((tid & 31) == 0) red[tid >> 5] = m;
    __syncthreads();
    m = red[0];
    #pragma unroll
    for (int w = 1; w < 8; w++) m = fmaxf(m, red[w]);

    float s = 0.f;
    #pragma unroll
    for (int i = 0; i < 4; i++) {
        v[i].x = expf(v[i].x - m); v[i].y = expf(v[i].y - m);
        v[i].z = expf(v[i].z - m); v[i].w = expf(v[i].w - m);
        s += v[i].x + v[i].y + v[i].z + v[i].w;
    }
    #pragma unroll
    for (int o = 16; o > 0; o >>= 1) s += __shfl_xor_sync(~0u, s, o);
    __syncthreads();
    if ((tid & 31) == 0) red[tid >> 5] = s;
    __syncthreads();
    s = 0.f;
    #pragma unroll
    for (int w = 0; w < 8; w++) s += red[w];

    const float inv = 1.f / s;
    #pragma unroll
    for (int i = 0; i < 4; i++) {
        v[i].x = rtf32(v[i].x * inv); v[i].y = rtf32(v[i].y * inv);
        v[i].z = rtf32(v[i].z * inv); v[i].w = rtf32(v[i].w * inv);
        ((float4*)row)[tid + i*256] = v[i];
    }
}

// ---------------- weight prep: transpose + concat, tf32-RN -----------------
__global__ void __launch_bounds__(256) prep_weights(
    const float* __restrict__ Wq, const float* __restrict__ bq,
    const float* __restrict__ Wk, const float* __restrict__ bk,
    const float* __restrict__ Wov)
{
    const int r = blockIdx.x, t = threadIdx.x;
    if (r < 256) {
        const int n = r & 127;
        const float* W = (r < 128) ? Wq : Wk;
        for (int e = t; e < EMBED; e += 256)
            g_Wqk[r*EMBED + e] = rtf32(W[(long)e*PROJ + n]);
        if (t == 0) g_bqk[r] = (r < 128) ? bq[n] : bk[n];
    } else {
        const int n = r - 256;
        for (int e = t; e < EMBED; e += 256)
            g_Wovt[(long)n*EMBED + e] = rtf32(Wov[(long)e*EMBED + n]);
    }
}

// ---------------- host ----------------
typedef CUresult (CUDAAPI *tmap_fn_t)(
    CUtensorMap*, CUtensorMapDataType, cuuint32_t, void*,
    const cuuint64_t*, const cuuint64_t*, const cuuint32_t*, const cuuint32_t*,
    CUtensorMapInterleave, CUtensorMapSwizzle, CUtensorMapL2promotion,
    CUtensorMapFloatOOBfill);

static void make_map(tmap_fn_t fn, CUtensorMap* m, void* base,
                     uint64_t d0, uint64_t d1, uint32_t b0, uint32_t b1)
{
    cuuint64_t dims[2]    = {d0, d1};
    cuuint64_t strides[1] = {d0 * 4};
    cuuint32_t box[2]     = {b0, b1};
    cuuint32_t es[2]      = {1, 1};
    fn(m, CU_TENSOR_MAP_DATA_TYPE_FLOAT32, 2, base, dims, strides, box, es,
       CU_TENSOR_MAP_INTERLEAVE_NONE, CU_TENSOR_MAP_SWIZZLE_128B,
       CU_TENSOR_MAP_L2_PROMOTION_L2_128B, CU_TENSOR_MAP_FLOAT_OOB_FILL_NONE);
}

extern "C" void kernel_launch(void* const* d_in, const int* in_sizes, int n_in,
                              void* d_out, int out_size)
{
    const float* x   = (const float*)d_in[0];
    const float* Wq  = (const float*)d_in[1];
    const float* bq  = (const float*)d_in[2];
    const float* Wk  = (const float*)d_in[3];
    const float* bk  = (const float*)d_in[4];
    const float* Wov = (const float*)d_in[5];
    const float* bov = (const float*)d_in[6];
    float* out = (float*)d_out;

    float *QK, *OVt, *S, *Wqk, *bqk, *Wovt;
    cudaGetSymbolAddress((void**)&QK,   g_QK);
    cudaGetSymbolAddress((void**)&OVt,  g_OVt);
    cudaGetSymbolAddress((void**)&S,    g_S);
    cudaGetSymbolAddress((void**)&Wqk,  g_Wqk);
    cudaGetSymbolAddress((void**)&bqk,  g_bqk);
    cudaGetSymbolAddress((void**)&Wovt, g_Wovt);

    cudaFuncSetAttribute(tc_gemm, cudaFuncAttributeMaxDynamicSharedMemorySize, SMEM_TOTAL);

    tmap_fn_t enc = nullptr;
    cudaDriverEntryPointQueryResult qr;
    cudaGetDriverEntryPointByVersion("cuTensorMapEncodeTiled", (void**)&enc,
                                     12000, cudaEnableDefault, &qr);

    CUtensorMap mX_A, mWqk_B, mWovt_B, mQK_A, mQK_B, mS_A, mOVt_B;
    make_map(enc, &mX_A,    (void*)x, 1024, 16384, 32, 128);
    make_map(enc, &mWqk_B,  Wqk,      1024,   256, 32, 256);
    make_map(enc, &mWovt_B, Wovt,     1024,  1024, 32, 256);
    make_map(enc, &mQK_A,   QK,        256, 16384, 32, 128);
    make_map(enc, &mQK_B,   QK,        256, 16384, 32, 256);
    make_map(enc, &mS_A,    S,        4096, 16384, 32, 128);
    make_map(enc, &mOVt_B,  OVt,     16384,  1024, 32, 256);

    const float scale = 0.08838834764831845f;   // 1/sqrt(128)

    prep_weights<<<1280, 256>>>(Wq, bq, Wk, bk, Wov);

    // QK = x @ [Wq|Wk] + [bq|bk]   -> g_QK [16384 x 256], tf32-rounded
    tc_gemm<<<dim3(1, 128, 1), 256, SMEM_TOTAL>>>(
        mX_A, mWqk_B, bqk, QK, 1024, 0, 0, 0, 0, 0, 256, 0, 1.f, 0, 1);

    // OV^T = (x @ Wov + bov)^T     -> g_OVt [1024 x 16384], tf32-rounded
    tc_gemm<<<dim3(4, 128, 1), 256, SMEM_TOTAL>>>(
        mX_A, mWovt_B, bov, OVt, 1024, 0, 0, 0, 0, 0, 16384, 0, 1.f, 1, 1);

    // S[b] = (Q[b] @ K[b]^T) * scale   (A cols 0..127 of QK, B cols 128..255)
    tc_gemm<<<dim3(16, 32, 4), 256, SMEM_TOTAL>>>(
        mQK_A, mQK_B, nullptr, S, 128, 0, 128, 0, 4096, 4096,
        4096, (long)SEQ * SEQ, scale, 0, 0);

    softmax4096<<<BATCH * SEQ, 256>>>(S);

    // out[b] = P[b] @ OV[b]   (B = OVt rows d, K-offset b*4096)
    tc_gemm<<<dim3(4, 32, 4), 256, SMEM_TOTAL>>>(
        mS_A, mOVt_B, nullptr, out, 4096, 0, 0, 4096, 4096, 0,
        1024, (long)SEQ * EMBED, 1.f, 0, 0);
}

// round 11
// speedup vs baseline: 20.7144x; 1.5974x over previous
#include <cuda_runtime.h>
#include <cuda.h>
#include <cuda_fp16.h>
#include <cstdint>
#include <math.h>

#define BATCH 4
#define SEQ 4096
#define EMBED 1024
#define PROJ 128
#define MTOT (BATCH*SEQ)   // 16384

// tcgen05 is arch-specific: only for the sm_103a/sm_100a pass; the plain
// compute_103 PTX pass compiles empty GEMM bodies (never selected at run).
#if defined(__CUDA_ARCH__) && (defined(__CUDA_ARCH_FEAT_SM103_ALL) || defined(__CUDA_ARCH_FEAT_SM100_ALL))
#define TC_OK 1
#else
#define TC_OK 0
#endif

// ---------------- scratch (device globals; allocation-free) ----------------
__device__ __half g_x  [(size_t)MTOT*EMBED];      // 32 MB  x in fp16
__device__ __half g_QK [(size_t)MTOT*256];        // 8 MB   Q|K concat fp16
__device__ __half g_OVt[(size_t)EMBED*MTOT];      // 32 MB  OV^T fp16
__device__ __half g_S  [(size_t)BATCH*SEQ*SEQ];   // 128 MB scores/pattern fp16
__device__ __half g_Wqk[256*EMBED];               // [Wq|Wk]^T fp16
__device__ float  g_bqk[256];
__device__ __half g_Wovt[(size_t)EMBED*EMBED];    // Wov^T fp16

// ---------------- tile config: stage = 128 bytes of K = 64 fp16 ------------
#define MT 128
#define NT 256
#define KB 64
#define ST 4
#define STAGE_A_BYTES (MT*128)
#define STAGE_B_BYTES (NT*128)
#define STAGE_BYTES   (STAGE_A_BYTES + STAGE_B_BYTES)
#define CTRL_BYTES    1024
#define SMEM_TOTAL    (CTRL_BYTES + ST*STAGE_BYTES)

// idesc kind::f16: dtype=F32(1)<<4, atype=F16(0)<<7, btype=F16(0)<<10,
// N/8<<17, M/16<<24; K-major both sides.
#define IDESC_F16 ((1u<<4) | ((NT/8u)<<17) | ((MT/16u)<<24))

__device__ __forceinline__ uint32_t smem_u32(const void* p) {
    uint32_t a;
    asm("{ .reg .u64 t; cvta.to.shared.u64 t, %1; cvt.u32.u64 %0, t; }" : "=r"(a) : "l"(p));
    return a;
}

#if TC_OK
// SW128 K-major smem descriptor: LBO=1, SBO=64, version=1, layout=2
__device__ __forceinline__ uint64_t make_desc(uint32_t addr) {
    const uint64_t base = (uint64_t(2) << 61) | (uint64_t(1) << 46)
                        | (uint64_t(64) << 32) | (uint64_t(1) << 16);
    return base | ((uint64_t)(addr >> 4) & 0x3FFF);
}

#define MBAR_INIT(a, c) \
    asm volatile("mbarrier.init.shared.b64 [%0], %1;" :: "r"(a), "r"(c) : "memory")
#define MBAR_EXPECT(a, b) \
    asm volatile("mbarrier.arrive.expect_tx.shared.b64 _, [%0], %1;" :: "r"(a), "r"(b) : "memory")
#define MBAR_WAIT(a, ph) do { \
    asm volatile("{\n\t.reg .pred P1;\n\t" \
        "WL_%=:\n\t" \
        "mbarrier.try_wait.parity.acquire.cta.shared::cta.b64 P1, [%0], %1, 0x989680;\n\t" \
        "@P1 bra WD_%=;\n\t" \
        "bra WL_%=;\n\t" \
        "WD_%=:\n\t}" \
        :: "r"(a), "r"(ph) : "memory"); \
} while (0)

__device__ __forceinline__ void tma2d(uint32_t dst, const CUtensorMap* m,
                                      int x, int y, uint32_t bar) {
    asm volatile(
        "cp.async.bulk.tensor.2d.shared::cta.global.tile.mbarrier::complete_tx::bytes "
        "[%0], [%1, {%2, %3}], [%4];"
        :: "r"(dst), "l"(m), "r"(x), "r"(y), "r"(bar) : "memory");
}

__device__ __forceinline__ void mma_f16(uint32_t d, uint64_t ad, uint64_t bd,
                                        uint32_t idesc, uint32_t en) {
    asm volatile(
        "{\n\t.reg .pred p;\n\tsetp.ne.u32 p, %4, 0;\n\t"
        "tcgen05.mma.cta_group::1.kind::f16 [%0], %1, %2, %3, {%5, %5, %5, %5}, p;\n\t}"
        :: "r"(d), "l"(ad), "l"(bd), "r"(idesc), "r"(en), "r"(0u) : "memory");
}

#define TC_COMMIT(bar) \
    asm volatile("tcgen05.commit.cta_group::1.mbarrier::arrive::one.shared::cluster.b64 [%0];" \
                 :: "r"(bar) : "memory")
#define TC_ALLOC(slot, n) \
    asm volatile("tcgen05.alloc.cta_group::1.sync.aligned.shared::cta.b32 [%0], %1;" \
                 :: "r"(slot), "r"(n) : "memory")
#define TC_DEALLOC(t, n) \
    asm volatile("tcgen05.dealloc.cta_group::1.sync.aligned.b32 %0, %1;" :: "r"(t), "r"(n))
#define TC_RELINQ() \
    asm volatile("tcgen05.relinquish_alloc_permit.cta_group::1.sync.aligned;")
#define TC_FENCE_AFTER()  asm volatile("tcgen05.fence::after_thread_sync;" ::: "memory")
#define TC_FENCE_BEFORE() asm volatile("tcgen05.fence::before_thread_sync;" ::: "memory")
#define TC_WAIT_LD()      asm volatile("tcgen05.wait::ld.sync.aligned;" ::: "memory")

#define TC_LD_X32(r, addr) \
    asm volatile( \
        "tcgen05.ld.sync.aligned.32x32b.x32.b32 " \
        "{%0, %1, %2, %3, %4, %5, %6, %7, " \
        " %8, %9, %10, %11, %12, %13, %14, %15, " \
        " %16, %17, %18, %19, %20, %21, %22, %23, " \
        " %24, %25, %26, %27, %28, %29, %30, %31}, [%32];" \
        : "=r"((r)[0]),  "=r"((r)[1]),  "=r"((r)[2]),  "=r"((r)[3]), \
          "=r"((r)[4]),  "=r"((r)[5]),  "=r"((r)[6]),  "=r"((r)[7]), \
          "=r"((r)[8]),  "=r"((r)[9]),  "=r"((r)[10]), "=r"((r)[11]), \
          "=r"((r)[12]), "=r"((r)[13]), "=r"((r)[14]), "=r"((r)[15]), \
          "=r"((r)[16]), "=r"((r)[17]), "=r"((r)[18]), "=r"((r)[19]), \
          "=r"((r)[20]), "=r"((r)[21]), "=r"((r)[22]), "=r"((r)[23]), \
          "=r"((r)[24]), "=r"((r)[25]), "=r"((r)[26]), "=r"((r)[27]), \
          "=r"((r)[28]), "=r"((r)[29]), "=r"((r)[30]), "=r"((r)[31]) \
        : "r"(addr))
#endif  // TC_OK

// ---------------------------------------------------------------------------
// tcgen05 fp16 GEMM: C[128x256 tile] = alpha * A @ B^T (+bias)
// A via mapA (box 64x128), B via mapB (box 64x256); fp16 K-major SW128.
// outMode: 0 = f32 row-major, 2 = f16 row-major, 3 = f16 transposed
// ---------------------------------------------------------------------------
__global__ void __launch_bounds__(256, 1) tc_gemm(
    const __grid_constant__ CUtensorMap mapA,
    const __grid_constant__ CUtensorMap mapB,
    const float* __restrict__ bias, void* __restrict__ Cv,
    int K, int xA0, int xB0, int szBx, int szAy, int szBy,
    int ldc, long szC, float alpha, int outMode)
{
#if TC_OK
    extern __shared__ __align__(1024) char smem[];
    const uint32_t sb = smem_u32(smem);
    const int tid = threadIdx.x, wid = tid >> 5;
    const int z = blockIdx.z;
    const int KT = K / KB;

    if (tid == 0) {
        #pragma unroll
        for (int s = 0; s < ST; s++) {
            MBAR_INIT(sb + s*16,     1);   // full
            MBAR_INIT(sb + s*16 + 8, 1);   // empty
        }
        MBAR_INIT(sb + 64, 1);             // done
    }
    if (wid == 0) TC_ALLOC(sb + 96, 256);
    __syncthreads();
    uint32_t tmem;
    asm volatile("ld.shared.b32 %0, [%1];" : "=r"(tmem) : "r"(sb + 96));

    if (tid == 224) {
        // ---- producer ----
        const int yA = blockIdx.y * MT + z * szAy;
        const int yB = blockIdx.x * NT + z * szBy;
        const int xB = xB0 + z * szBx;
        int s = 0, ph = 1;
        for (int kt = 0; kt < KT; kt++) {
            MBAR_WAIT(sb + s*16 + 8, ph);
            MBAR_EXPECT(sb + s*16, STAGE_BYTES);
            const uint32_t stg = sb + CTRL_BYTES + s * STAGE_BYTES;
            tma2d(stg,                 &mapA, xA0 + kt*KB, yA, sb + s*16);
            tma2d(stg + STAGE_A_BYTES, &mapB, xB  + kt*KB, yB, sb + s*16);
            if (++s == ST) { s = 0; ph ^= 1; }
        }
    } else if (tid == 192) {
        // ---- MMA issuer: 4 x K=16 per 64-K stage ----
        uint64_t ad[ST], bd[ST];
        #pragma unroll
        for (int s = 0; s < ST; s++) {
            ad[s] = make_desc(sb + CTRL_BYTES + s * STAGE_BYTES);
            bd[s] = make_desc(sb + CTRL_BYTES + s * STAGE_BYTES + STAGE_A_BYTES);
        }
        int s = 0, ph = 0;
        for (int kt = 0; kt < KT; kt++) {
            MBAR_WAIT(sb + s*16, ph);
            #pragma unroll
            for (int j = 0; j < 4; j++)
                mma_f16(tmem, ad[s] + j*2, bd[s] + j*2, IDESC_F16,
                        (uint32_t)((kt | j) != 0));
            TC_COMMIT(sb + s*16 + 8);
            if (++s == ST) { s = 0; ph ^= 1; }
        }
        TC_COMMIT(sb + 64);
    }

    MBAR_WAIT(sb + 64, 0);
    TC_FENCE_AFTER();

    // ---- epilogue: warps 0-3, lane m = tid (0..127) ----
    if (wid < 4) {
        const int ml = tid;
        #pragma unroll
        for (int nc = 0; nc < NT/32; nc++) {
            uint32_t r[32];
            TC_LD_X32(r, tmem + nc*32);
            TC_WAIT_LD();
            const int nbase = blockIdx.x * NT + nc * 32;
            if (outMode == 0) {                       // f32 row-major (final out)
                float* Cz = (float*)Cv + (long)z * szC;
                float4* dst = (float4*)(Cz + ((long)blockIdx.y*MT + ml) * ldc + nbase);
                #pragma unroll
                for (int j = 0; j < 8; j++) {
                    float4 bv = make_float4(0.f, 0.f, 0.f, 0.f);
                    if (bias) bv = *(const float4*)(bias + nbase + 4*j);
                    float4 o;
                    o.x = alpha * __uint_as_float(r[4*j+0]) + bv.x;
                    o.y = alpha * __uint_as_float(r[4*j+1]) + bv.y;
                    o.z = alpha * __uint_as_float(r[4*j+2]) + bv.z;
                    o.w = alpha * __uint_as_float(r[4*j+3]) + bv.w;
                    dst[j] = o;
                }
            } else if (outMode == 2) {                // f16 row-major (QK, scores)
                __half* Cz = (__half*)Cv + (long)z * szC;
                uint32_t p[16];
                #pragma unroll
                for (int j = 0; j < 16; j++) {
                    float lo = alpha * __uint_as_float(r[2*j+0]);
                    float hi = alpha * __uint_as_float(r[2*j+1]);
                    if (bias) { lo += __ldg(bias + nbase + 2*j); hi += __ldg(bias + nbase + 2*j + 1); }
                    __half2 h = __floats2half2_rn(lo, hi);
                    p[j] = *(uint32_t*)&h;
                }
                uint4* dst = (uint4*)(Cz + ((long)blockIdx.y*MT + ml) * ldc + nbase);
                #pragma unroll
                for (int q = 0; q < 4; q++)
                    dst[q] = make_uint4(p[4*q], p[4*q+1], p[4*q+2], p[4*q+3]);
            } else {                                  // f16 transposed (OV^T)
                __half* Cz = (__half*)Cv + (long)z * szC;
                #pragma unroll
                for (int i = 0; i < 32; i++) {
                    const int n = nbase + i;
                    float v = alpha * __uint_as_float(r[i]) + (bias ? __ldg(bias + n) : 0.f);
                    Cz[(long)n * ldc + blockIdx.y*MT + ml] = __float2half_rn(v);
                }
            }
        }
        TC_FENCE_BEFORE();
    }
    __syncthreads();
    if (wid == 0) { TC_RELINQ(); TC_DEALLOC(tmem, 256); }
#endif  // TC_OK
}

// ---------------- fp16 softmax over 4096-wide rows --------------------------
__global__ void __launch_bounds__(256) softmax4096(__half* __restrict__ S)
{
    __half* row = S + (size_t)blockIdx.x * 4096;
    const int tid = threadIdx.x;

    uint4 u[2];
    float v[16];
    #pragma unroll
    for (int i = 0; i < 2; i++) u[i] = ((const uint4*)row)[tid + i*256];
    #pragma unroll
    for (int i = 0; i < 2; i++) {
        const uint32_t* w = (const uint32_t*)&u[i];
        #pragma unroll
        for (int q = 0; q < 4; q++) {
            float2 f = __half22float2(*(const __half2*)&w[q]);
            v[i*8 + 2*q]     = f.x;
            v[i*8 + 2*q + 1] = f.y;
        }
    }

    float m = -1e30f;
    #pragma unroll
    for (int i = 0; i < 16; i++) m = fmaxf(m, v[i]);
    __shared__ float red[8];
    #pragma unroll
    for (int o = 16; o > 0; o >>= 1) m = fmaxf(m, __shfl_xor_sync(~0u, m, o));
    if ((tid & 31) == 0) red[tid >> 5] = m;
    __syncthreads();
    m = red[0];
    #pragma unroll
    for (int w = 1; w < 8; w++) m = fmaxf(m, red[w]);

    float s = 0.f;
    #pragma unroll
    for (int i = 0; i < 16; i++) { v[i] = expf(v[i] - m); s += v[i]; }
    #pragma unroll
    for (int o = 16; o > 0; o >>= 1) s += __shfl_xor_sync(~0u, s, o);
    __syncthreads();
    if ((tid & 31) == 0) red[tid >> 5] = s;
    __syncthreads();
    s = 0.f;
    #pragma unroll
    for (int w = 0; w < 8; w++) s += red[w];

    const float inv = 1.f / s;
    #pragma unroll
    for (int i = 0; i < 2; i++) {
        uint32_t* w = (uint32_t*)&u[i];
        #pragma unroll
        for (int q = 0; q < 4; q++) {
            __half2 h = __floats2half2_rn(v[i*8 + 2*q] * inv, v[i*8 + 2*q + 1] * inv);
            w[q] = *(uint32_t*)&h;
        }
        ((uint4*)row)[tid + i*256] = u[i];
    }
}

// ---------------- x -> fp16 copy -------------------------------------------
__global__ void __launch_bounds__(256) cvt_x(const float* __restrict__ x)
{
    const size_t i = ((size_t)blockIdx.x * 256 + threadIdx.x) * 8;
    float4 a = *(const float4*)(x + i);
    float4 b = *(const float4*)(x + i + 4);
    __half2 h0 = __floats2half2_rn(a.x, a.y);
    __half2 h1 = __floats2half2_rn(a.z, a.w);
    __half2 h2 = __floats2half2_rn(b.x, b.y);
    __half2 h3 = __floats2half2_rn(b.z, b.w);
    uint4 o = make_uint4(*(uint32_t*)&h0, *(uint32_t*)&h1,
                         *(uint32_t*)&h2, *(uint32_t*)&h3);
    *(uint4*)(g_x + i) = o;
}

// ---------------- weight prep: transpose + concat -> fp16 ------------------
__global__ void __launch_bounds__(256) prep_weights(
    const float* __restrict__ Wq, const float* __restrict__ bq,
    const float* __restrict__ Wk, const float* __restrict__ bk,
    const float* __restrict__ Wov)
{
    const int r = blockIdx.x, t = threadIdx.x;
    if (r < 256) {
        const int n = r & 127;
        const float* W = (r < 128) ? Wq : Wk;
        for (int e = t; e < EMBED; e += 256)
            g_Wqk[r*EMBED + e] = __float2half_rn(W[(long)e*PROJ + n]);
        if (t == 0) g_bqk[r] = (r < 128) ? bq[n] : bk[n];
    } else {
        const int n = r - 256;
        for (int e = t; e < EMBED; e += 256)
            g_Wovt[(long)n*EMBED + e] = __float2half_rn(Wov[(long)e*EMBED + n]);
    }
}

// ---------------- host ----------------
typedef CUresult (CUDAAPI *tmap_fn_t)(
    CUtensorMap*, CUtensorMapDataType, cuuint32_t, void*,
    const cuuint64_t*, const cuuint64_t*, const cuuint32_t*, const cuuint32_t*,
    CUtensorMapInterleave, CUtensorMapSwizzle, CUtensorMapL2promotion,
    CUtensorMapFloatOOBfill);

static void make_map(tmap_fn_t fn, CUtensorMap* m, void* base,
                     uint64_t d0, uint64_t d1, uint32_t b0, uint32_t b1)
{
    cuuint64_t dims[2]    = {d0, d1};
    cuuint64_t strides[1] = {d0 * 2};
    cuuint32_t box[2]     = {b0, b1};
    cuuint32_t es[2]      = {1, 1};
    fn(m, CU_TENSOR_MAP_DATA_TYPE_FLOAT16, 2, base, dims, strides, box, es,
       CU_TENSOR_MAP_INTERLEAVE_NONE, CU_TENSOR_MAP_SWIZZLE_128B,
       CU_TENSOR_MAP_L2_PROMOTION_L2_128B, CU_TENSOR_MAP_FLOAT_OOB_FILL_NONE);
}

extern "C" void kernel_launch(void* const* d_in, const int* in_sizes, int n_in,
                              void* d_out, int out_size)
{
    const float* x   = (const float*)d_in[0];
    const float* Wq  = (const float*)d_in[1];
    const float* bq  = (const float*)d_in[2];
    const float* Wk  = (const float*)d_in[3];
    const float* bk  = (const float*)d_in[4];
    const float* Wov = (const float*)d_in[5];
    const float* bov = (const float*)d_in[6];
    float* out = (float*)d_out;

    __half *xh, *QK, *OVt, *S, *Wqk, *Wovt;
    float *bqk;
    cudaGetSymbolAddress((void**)&xh,   g_x);
    cudaGetSymbolAddress((void**)&QK,   g_QK);
    cudaGetSymbolAddress((void**)&OVt,  g_OVt);
    cudaGetSymbolAddress((void**)&S,    g_S);
    cudaGetSymbolAddress((void**)&Wqk,  g_Wqk);
    cudaGetSymbolAddress((void**)&bqk,  g_bqk);
    cudaGetSymbolAddress((void**)&Wovt, g_Wovt);

    cudaFuncSetAttribute(tc_gemm, cudaFuncAttributeMaxDynamicSharedMemorySize, SMEM_TOTAL);

    tmap_fn_t enc = nullptr;
    cudaDriverEntryPointQueryResult qr;
    cudaGetDriverEntryPointByVersion("cuTensorMapEncodeTiled", (void**)&enc,
                                     12000, cudaEnableDefault, &qr);

    CUtensorMap mX_A, mWqk_B, mWovt_B, mQK_A, mQK_B, mS_A, mOVt_B;
    make_map(enc, &mX_A,    xh,   1024, 16384, 64, 128);
    make_map(enc, &mWqk_B,  Wqk,  1024,   256, 64, 256);
    make_map(enc, &mWovt_B, Wovt, 1024,  1024, 64, 256);
    make_map(enc, &mQK_A,   QK,    256, 16384, 64, 128);
    make_map(enc, &mQK_B,   QK,    256, 16384, 64, 256);
    make_map(enc, &mS_A,    S,    4096, 16384, 64, 128);
    make_map(enc, &mOVt_B,  OVt, 16384,  1024, 64, 256);

    const float scale = 0.08838834764831845f;   // 1/sqrt(128)

    cvt_x<<<MTOT*EMBED/(256*8), 256>>>(x);
    prep_weights<<<1280, 256>>>(Wq, bq, Wk, bk, Wov);

    // QK = x @ [Wq|Wk] + [bq|bk]  -> g_QK fp16 [16384 x 256]
    tc_gemm<<<dim3(1, 128, 1), 256, SMEM_TOTAL>>>(
        mX_A, mWqk_B, bqk, QK, 1024, 0, 0, 0, 0, 0, 256, 0, 1.f, 2);

    // OV^T = (x @ Wov + bov)^T   -> g_OVt fp16 [1024 x 16384]
    tc_gemm<<<dim3(4, 128, 1), 256, SMEM_TOTAL>>>(
        mX_A, mWovt_B, bov, OVt, 1024, 0, 0, 0, 0, 0, 16384, 0, 1.f, 3);

    // S[b] = (Q[b] @ K[b]^T) * scale  -> g_S fp16
    tc_gemm<<<dim3(16, 32, 4), 256, SMEM_TOTAL>>>(
        mQK_A, mQK_B, nullptr, S, 128, 0, 128, 0, 4096, 4096,
        4096, (long)SEQ * SEQ, scale, 2);

    softmax4096<<<BATCH * SEQ, 256>>>(S);

    // out[b] = P[b] @ OV[b]  -> fp32 out
    tc_gemm<<<dim3(4, 32, 4), 256, SMEM_TOTAL>>>(
        mS_A, mOVt_B, nullptr, out, 4096, 0, 0, 4096, 4096, 0,
        1024, (long)SEQ * EMBED, 1.f, 0);
}